// round 3
// baseline (speedup 1.0000x reference)
#include <cuda_runtime.h>
#include <math.h>
#include <stdint.h>

#define BB 2
#define SS 2048
#define HIDD 1024
#define HH 16
#define DD 64
#define KKEEP 204
#define QT 8
#define CK 256
#define CKP 260
#define DC 16

// ---------------- device scratch (static __device__ arrays are allowed) ----------------
__device__ float g_Q[BB*HH*SS*DD];    // [b,h,s,d]
__device__ float g_K[BB*HH*SS*DD];
__device__ float g_V[BB*HH*SS*DD];
__device__ float g_AO[BB*SS*HIDD];    // attention output, [b,s,hid]
__device__ float g_Vsum[BB*HH*DD];    // per-(b,h) column sum of V

// ---------------- GEMM: C[M,N] = A[M,1024] @ W[1024,N] + bias ----------------
// BM=BN=128, BK=8, 256 threads, 8x8 per thread.
// dst: 0 -> g_Q, 1 -> g_K, 2 -> g_V (all [b,h,s,d]); 3 -> C_out ([m,1024])
__global__ __launch_bounds__(256)
void gemm128(const float* __restrict__ A, const float* __restrict__ W,
             const float* __restrict__ bias, float* __restrict__ C_out,
             int dst)
{
    __shared__ float As[8][132];
    __shared__ float Bs[8][128];
    const int bm = blockIdx.y * 128;
    const int bn = blockIdx.x * 128;
    const int t  = threadIdx.x;
    const int tx = t & 15, ty = t >> 4;

    float acc[8][8];
#pragma unroll
    for (int i = 0; i < 8; i++)
#pragma unroll
        for (int j = 0; j < 8; j++) acc[i][j] = 0.f;

    const int ar = t >> 1, ac4 = (t & 1) * 4;
    const int br = t >> 5, bc4 = (t & 31) * 4;

    for (int k0 = 0; k0 < 1024; k0 += 8) {
        // A tile (128x8), stored transposed
        float4 av = *(const float4*)&A[(size_t)(bm + ar) * 1024 + k0 + ac4];
        As[ac4+0][ar] = av.x; As[ac4+1][ar] = av.y;
        As[ac4+2][ar] = av.z; As[ac4+3][ar] = av.w;
        // W tile (8x128)
        *(float4*)&Bs[br][bc4] = *(const float4*)&W[(size_t)(k0 + br) * 1024 + bn + bc4];
        __syncthreads();
#pragma unroll
        for (int kk = 0; kk < 8; kk++) {
            float a[8], b[8];
            *(float4*)&a[0] = *(float4*)&As[kk][ty*8];
            *(float4*)&a[4] = *(float4*)&As[kk][ty*8+4];
            *(float4*)&b[0] = *(float4*)&Bs[kk][tx*8];
            *(float4*)&b[4] = *(float4*)&Bs[kk][tx*8+4];
#pragma unroll
            for (int i = 0; i < 8; i++)
#pragma unroll
                for (int j = 0; j < 8; j++) acc[i][j] += a[i] * b[j];
        }
        __syncthreads();
    }

    float* Chead = (dst == 0) ? g_Q : (dst == 1) ? g_K : (dst == 2) ? g_V : C_out;

#pragma unroll
    for (int i = 0; i < 8; i++) {
        int m = bm + ty*8 + i;
#pragma unroll
        for (int j = 0; j < 8; j++) {
            int n = bn + tx*8 + j;
            float v = acc[i][j] + bias[n];
            if (dst < 3) {
                int b_ = m >> 11, s = m & 2047;
                int h  = n >> 6,  d = n & 63;
                Chead[((((size_t)b_*HH + h)*SS + s))*DD + d] = v;
            } else {
                Chead[(size_t)m * HIDD + n] = v;
            }
        }
    }
}

// ---------------- per-(b,h) V column sums ----------------
__global__ void vsum_kernel()
{
    int bh = blockIdx.x;
    int d  = threadIdx.x;  // 64 threads
    const float* vp = g_V + (size_t)bh*SS*DD + d;
    float s0=0,s1=0,s2=0,s3=0;
    for (int i = 0; i < SS; i += 4) {
        s0 += vp[(size_t)(i+0)*DD];
        s1 += vp[(size_t)(i+1)*DD];
        s2 += vp[(size_t)(i+2)*DD];
        s3 += vp[(size_t)(i+3)*DD];
    }
    g_Vsum[bh*DD + d] = (s0+s1)+(s2+s3);
}

// ---------------- fused attention: scores + exact top-k + sparse softmax@V ----------------
__device__ __forceinline__ unsigned fkey(float f)
{
    unsigned u = __float_as_uint(f);
    return (u & 0x80000000u) ? ~u : (u | 0x80000000u);  // monotonic ascending
}

__global__ __launch_bounds__(256, 2)
void attn_kernel()
{
    extern __shared__ float smem[];
    float* sc   = smem;                     // [QT][SS]
    float* Kt   = sc + QT*SS;               // [DC][CKP] transposed K chunk
    float* Qs   = Kt + DC*CKP;              // [QT][DD]
    int*   hist = (int*)(Qs + QT*DD);       // [8][256]
    int*   sel  = hist + 8*256;             // [QT][KKEEP]
    int*   wsi  = sel + QT*KKEEP;           // [8][4] warp scratch

    const int t    = threadIdx.x;
    const int tile = blockIdx.x;
    const int bh   = tile / (SS/QT);
    const int q0   = (tile % (SS/QT)) * QT;
    const float* Qg = g_Q + (size_t)bh*SS*DD;
    const float* Kg = g_K + (size_t)bh*SS*DD;
    const float* Vg = g_V + (size_t)bh*SS*DD;

    // load Q rows
    if (t < 128) {
        int r = t >> 4, c = (t & 15) * 4;
        *(float4*)&Qs[r*DD + c] = *(const float4*)&Qg[(size_t)(q0 + r)*DD + c];
    }
    __syncthreads();

    // ---- phase A: scores, 2q x 4k register tile ----
    const float scale = 0.125f;  // 1/sqrt(64)
    const int kq = t >> 6;       // q group 0..3 -> rows kq, kq+4
    const int k0 = (t & 63) * 4; // 4 keys

    for (int kc = 0; kc < SS; kc += CK) {
        float acc0[4] = {0.f,0.f,0.f,0.f};
        float acc1[4] = {0.f,0.f,0.f,0.f};
        for (int dc = 0; dc < DD; dc += DC) {
            // load K chunk transposed: Kt[dlocal][key]
#pragma unroll
            for (int it = 0; it < 4; it++) {
                int idx = it * 256 + t;
                int key = idx >> 2;
                int jj  = idx & 3;
                float4 v = *(const float4*)&Kg[(size_t)(kc + key)*DD + dc + jj*4];
                Kt[(jj*4+0)*CKP + key] = v.x;
                Kt[(jj*4+1)*CKP + key] = v.y;
                Kt[(jj*4+2)*CKP + key] = v.z;
                Kt[(jj*4+3)*CKP + key] = v.w;
            }
            __syncthreads();
#pragma unroll
            for (int d4 = 0; d4 < DC; d4 += 4) {
                float qa[4], qb[4], kv[4][4];
                *(float4*)qa = *(float4*)&Qs[kq*DD + dc + d4];
                *(float4*)qb = *(float4*)&Qs[(kq+4)*DD + dc + d4];
#pragma unroll
                for (int dd = 0; dd < 4; dd++)
                    *(float4*)kv[dd] = *(float4*)&Kt[(d4+dd)*CKP + k0];
#pragma unroll
                for (int dd = 0; dd < 4; dd++)
#pragma unroll
                    for (int j = 0; j < 4; j++) {
                        acc0[j] += qa[dd] * kv[dd][j];
                        acc1[j] += qb[dd] * kv[dd][j];
                    }
            }
            __syncthreads();
        }
        *(float4*)&sc[kq*SS + kc + k0] =
            make_float4(acc0[0]*scale, acc0[1]*scale, acc0[2]*scale, acc0[3]*scale);
        *(float4*)&sc[(kq+4)*SS + kc + k0] =
            make_float4(acc1[0]*scale, acc1[1]*scale, acc1[2]*scale, acc1[3]*scale);
    }
    __syncthreads();

    // ---- phase B: per-warp exact top-204 radix select + softmax stats ----
    const int w = t >> 5, lane = t & 31;
    const unsigned ltmask = (1u << lane) - 1u;
    const int qi = w;
    const float* row = sc + qi*SS;

    float rmax = -1e30f;
    for (int i = lane; i < SS; i += 32) rmax = fmaxf(rmax, row[i]);
#pragma unroll
    for (int off = 16; off; off >>= 1)
        rmax = fmaxf(rmax, __shfl_xor_sync(~0u, rmax, off));
    const float m = fmaxf(rmax, 0.0f);  // max of sparse row (zeros present)

    int rem = KKEEP;
    unsigned prefix = 0;
    int* h = hist + w*256;
#pragma unroll
    for (int pass = 0; pass < 4; pass++) {
        int shift = 24 - pass*8;
        for (int i = lane; i < 256; i += 32) h[i] = 0;
        __syncwarp();
        for (int i = lane; i < SS; i += 32) {
            unsigned u = fkey(row[i]);
            if (pass == 0 || (u >> (shift + 8)) == prefix)
                atomicAdd(&h[(u >> shift) & 255], 1);
        }
        __syncwarp();
        if (lane == 0) {
            int cum = 0, bsel = 0, r2 = rem;
            for (int bbin = 255; bbin >= 0; bbin--) {
                int c = h[bbin];
                if (cum + c >= rem) { bsel = bbin; r2 = rem - cum; break; }
                cum += c;
            }
            wsi[w*4+0] = bsel;
            wsi[w*4+1] = r2;
        }
        __syncwarp();
        prefix = (prefix << 8) | (unsigned)wsi[w*4+0];
        rem = wsi[w*4+1];
    }
    const unsigned T = prefix;   // key of the 204th largest
    const int need_eq = rem;     // how many == T to take (lowest index first)

    // build selection list (index-ordered tie-break, matches jax top_k) + Z
    int cnt = 0, eqtaken = 0;
    float zacc = 0.f;
    for (int i0 = 0; i0 < SS; i0 += 32) {
        int i = i0 + lane;
        float v = row[i];
        unsigned u = fkey(v);
        bool gt = u > T;
        bool eq = (u == T);
        unsigned em = __ballot_sync(~0u, eq);
        bool seleq = eq && (eqtaken + __popc(em & ltmask)) < need_eq;
        eqtaken += __popc(em);
        bool selected = gt || seleq;
        unsigned smk = __ballot_sync(~0u, selected);
        int pos = cnt + __popc(smk & ltmask);
        cnt += __popc(smk);
        if (selected && pos < KKEEP) {
            sel[qi*KKEEP + pos] = i;
            zacc += __expf(v - m);
        }
    }
#pragma unroll
    for (int off = 16; off; off >>= 1)
        zacc += __shfl_xor_sync(~0u, zacc, off);
    const float e0 = __expf(-m);
    const float Z = zacc + (float)(SS - KKEEP) * e0;
    const float invZ = 1.0f / Z;

    // ---- phase C: out = (sum_sel (e_i - e0) V_i + e0 * Vsum) / Z ----
    // lane covers d pairs {2*lane, 2*lane+1} via float2 loads (halves LDG count)
    const int d0 = 2*lane;
    float2 a = *(const float2*)&g_Vsum[bh*DD + d0];
    a.x *= e0; a.y *= e0;
#pragma unroll 2
    for (int j = 0; j < KKEEP; j++) {
        int idx = sel[qi*KKEEP + j];
        float v = row[idx];
        float wgt = __expf(v - m) - e0;
        float2 vr = *(const float2*)&Vg[(size_t)idx * DD + d0];
        a.x += wgt * vr.x;
        a.y += wgt * vr.y;
    }
    const int b_ = bh / HH, hh = bh % HH;
    float* ao = g_AO + ((size_t)(b_*SS + q0 + qi))*HIDD + hh*DD;
    ao[d0]   = a.x * invZ;
    ao[d0+1] = a.y * invZ;
}

// ---------------- launcher ----------------
extern "C" void kernel_launch(void* const* d_in, const int* in_sizes, int n_in,
                              void* d_out, int out_size)
{
    (void)in_sizes; (void)n_in; (void)out_size;
    const float* x  = (const float*)d_in[0];
    const float* Wq = (const float*)d_in[1];
    const float* bq = (const float*)d_in[2];
    const float* Wk = (const float*)d_in[3];
    const float* bk = (const float*)d_in[4];
    const float* Wv = (const float*)d_in[5];
    const float* bv = (const float*)d_in[6];
    const float* Wo = (const float*)d_in[7];
    const float* bo = (const float*)d_in[8];
    float* out = (float*)d_out;

    const int smem_bytes = (QT*SS + DC*CKP + QT*DD)*4 + (8*256 + QT*KKEEP + 32)*4;
    cudaFuncSetAttribute(attn_kernel, cudaFuncAttributeMaxDynamicSharedMemorySize,
                         smem_bytes);

    float* AOp;
    cudaGetSymbolAddress((void**)&AOp, g_AO);

    dim3 gproj(HIDD/128, (BB*SS)/128);  // 8 x 32
    gemm128<<<gproj, 256>>>(x, Wq, bq, nullptr, 0);
    gemm128<<<gproj, 256>>>(x, Wk, bk, nullptr, 1);
    gemm128<<<gproj, 256>>>(x, Wv, bv, nullptr, 2);

    vsum_kernel<<<BB*HH, DD>>>();

    attn_kernel<<<BB*HH*(SS/QT), 256, smem_bytes>>>();

    gemm128<<<gproj, 256>>>(AOp, Wo, bo, out, 3);
}

// round 6
// speedup vs baseline: 1.3148x; 1.3148x over previous
#include <cuda_runtime.h>
#include <math.h>
#include <stdint.h>

#define BB 2
#define SS 2048
#define HIDD 1024
#define HH 16
#define DD 64
#define KKEEP 204
#define QT 16
#define CK 512
#define CKP 516  // 516*4 % 16 == 0 -> float4-aligned rows; 516%32=4 keeps reads conflict-free
#define DC 16
#define PA 132   // 132*4 % 16 == 0 -> float4-aligned rows

// ---------------- device scratch ----------------
__device__ float g_Q[BB*HH*SS*DD];    // [b,h,s,d]
__device__ float g_K[BB*HH*SS*DD];
__device__ float g_V[BB*HH*SS*DD];
__device__ float g_AO[BB*SS*HIDD];    // attention output, [b,s,hid]
__device__ float g_Vsum[BB*HH*DD];    // per-(b,h) column sum of V

// =====================================================================
// GEMM core: 128x128 tile, BK=16, double-buffered, 256 thr, 8x8/thread
// (split 4+4 register tile)
// =====================================================================
struct GemmAcc { float a[8][8]; };

__device__ __forceinline__ void gemm_core(
    const float* __restrict__ A, const float* __restrict__ W,
    int bm, int bn, int t,
    float (*As)[16][PA], float (*Bs)[16][128], GemmAcc& R)
{
#pragma unroll
    for (int i = 0; i < 8; i++)
#pragma unroll
        for (int j = 0; j < 8; j++) R.a[i][j] = 0.f;

    const int ar0 = t >> 2, ac4 = (t & 3) * 4;   // A: rows ar0, ar0+64
    const int bk0 = t >> 5, bc4 = (t & 31) * 4;  // B: k-rows bk0, bk0+8

    float4 a0, a1, b0, b1;
    // prologue load k0 = 0
    a0 = *(const float4*)&A[(size_t)(bm + ar0     ) * HIDD + ac4];
    a1 = *(const float4*)&A[(size_t)(bm + ar0 + 64) * HIDD + ac4];
    b0 = *(const float4*)&W[(size_t)(bk0    ) * HIDD + bn + bc4];
    b1 = *(const float4*)&W[(size_t)(bk0 + 8) * HIDD + bn + bc4];
    {
        As[0][ac4+0][ar0] = a0.x; As[0][ac4+1][ar0] = a0.y;
        As[0][ac4+2][ar0] = a0.z; As[0][ac4+3][ar0] = a0.w;
        As[0][ac4+0][ar0+64] = a1.x; As[0][ac4+1][ar0+64] = a1.y;
        As[0][ac4+2][ar0+64] = a1.z; As[0][ac4+3][ar0+64] = a1.w;
        *(float4*)&Bs[0][bk0  ][bc4] = b0;
        *(float4*)&Bs[0][bk0+8][bc4] = b1;
    }
    __syncthreads();

    int buf = 0;
    const int tx = t & 15, ty = t >> 4;
    for (int k0 = 16; ; k0 += 16) {
        const bool more = (k0 < HIDD);
        if (more) {
            a0 = *(const float4*)&A[(size_t)(bm + ar0     ) * HIDD + k0 + ac4];
            a1 = *(const float4*)&A[(size_t)(bm + ar0 + 64) * HIDD + k0 + ac4];
            b0 = *(const float4*)&W[(size_t)(k0 + bk0    ) * HIDD + bn + bc4];
            b1 = *(const float4*)&W[(size_t)(k0 + bk0 + 8) * HIDD + bn + bc4];
        }
#pragma unroll
        for (int kk = 0; kk < 16; kk++) {
            float a[8], b[8];
            *(float4*)&a[0] = *(float4*)&As[buf][kk][ty*4];
            *(float4*)&a[4] = *(float4*)&As[buf][kk][64 + ty*4];
            *(float4*)&b[0] = *(float4*)&Bs[buf][kk][tx*4];
            *(float4*)&b[4] = *(float4*)&Bs[buf][kk][64 + tx*4];
#pragma unroll
            for (int i = 0; i < 8; i++)
#pragma unroll
                for (int j = 0; j < 8; j++) R.a[i][j] += a[i] * b[j];
        }
        if (!more) break;
        const int nb = buf ^ 1;
        As[nb][ac4+0][ar0] = a0.x; As[nb][ac4+1][ar0] = a0.y;
        As[nb][ac4+2][ar0] = a0.z; As[nb][ac4+3][ar0] = a0.w;
        As[nb][ac4+0][ar0+64] = a1.x; As[nb][ac4+1][ar0+64] = a1.y;
        As[nb][ac4+2][ar0+64] = a1.z; As[nb][ac4+3][ar0+64] = a1.w;
        *(float4*)&Bs[nb][bk0  ][bc4] = b0;
        *(float4*)&Bs[nb][bk0+8][bc4] = b1;
        __syncthreads();
        buf = nb;
    }
}

__device__ __forceinline__ int row_of(int i, int tyx) {
    return (i < 4) ? (tyx*4 + i) : (64 + tyx*4 + i - 4);
}

// fused Q/K/V projections: grid (8, 32, 3)
__global__ __launch_bounds__(256, 2)
void gemm_qkv(const float* __restrict__ x,
              const float* __restrict__ Wq, const float* __restrict__ bq,
              const float* __restrict__ Wk, const float* __restrict__ bk,
              const float* __restrict__ Wv, const float* __restrict__ bv)
{
    __shared__ float As[2][16][PA];
    __shared__ float Bs[2][16][128];
    const int z = blockIdx.z;
    const float* W    = (z == 0) ? Wq : (z == 1) ? Wk : Wv;
    const float* bias = (z == 0) ? bq : (z == 1) ? bk : bv;
    float* C          = (z == 0) ? g_Q : (z == 1) ? g_K : g_V;

    const int bm = blockIdx.y * 128, bn = blockIdx.x * 128;
    const int t = threadIdx.x, tx = t & 15, ty = t >> 4;
    GemmAcc R;
    gemm_core(x, W, bm, bn, t, As, Bs, R);

#pragma unroll
    for (int i = 0; i < 8; i++) {
        const int m = bm + row_of(i, ty);
        const int b_ = m >> 11, s = m & 2047;
#pragma unroll
        for (int j = 0; j < 8; j++) {
            const int n = bn + row_of(j, tx);
            const int h = n >> 6, d = n & 63;
            C[(((size_t)(b_*HH + h))*SS + s)*DD + d] = R.a[i][j] + bias[n];
        }
    }
}

// output projection: grid (8, 32)
__global__ __launch_bounds__(256, 2)
void gemm_o(const float* __restrict__ Wo, const float* __restrict__ bo,
            float* __restrict__ out)
{
    __shared__ float As[2][16][PA];
    __shared__ float Bs[2][16][128];
    const int bm = blockIdx.y * 128, bn = blockIdx.x * 128;
    const int t = threadIdx.x, tx = t & 15, ty = t >> 4;
    GemmAcc R;
    gemm_core(g_AO, Wo, bm, bn, t, As, Bs, R);

#pragma unroll
    for (int i = 0; i < 8; i++) {
        const int m = bm + row_of(i, ty);
#pragma unroll
        for (int j = 0; j < 8; j++) {
            const int n = bn + row_of(j, tx);
            out[(size_t)m * HIDD + n] = R.a[i][j] + bo[n];
        }
    }
}

// ---------------- per-(b,h) V column sums: grid 32, block 512 ----------------
__global__ __launch_bounds__(512)
void vsum_kernel()
{
    __shared__ float red[8][64];
    const int bh = blockIdx.x;
    const int d = threadIdx.x & 63, sub = threadIdx.x >> 6;  // 8 subs x 256 rows
    const float* vp = g_V + (size_t)bh*SS*DD + (size_t)sub*256*DD + d;
    float s0=0,s1=0,s2=0,s3=0;
#pragma unroll 4
    for (int i = 0; i < 256; i += 4) {
        s0 += vp[(size_t)(i+0)*DD];
        s1 += vp[(size_t)(i+1)*DD];
        s2 += vp[(size_t)(i+2)*DD];
        s3 += vp[(size_t)(i+3)*DD];
    }
    red[sub][d] = (s0+s1)+(s2+s3);
    __syncthreads();
    if (sub == 0) {
        float a = 0.f;
#pragma unroll
        for (int j = 0; j < 8; j++) a += red[j][d];
        g_Vsum[bh*DD + d] = a;
    }
}

// =====================================================================
// fused attention: scores (QT=16 rows) + exact top-204 + sparse softmax@V
// =====================================================================
__device__ __forceinline__ unsigned fkey(float f)
{
    unsigned u = __float_as_uint(f);
    return (u & 0x80000000u) ? ~u : (u | 0x80000000u);  // monotonic ascending
}

__global__ __launch_bounds__(512, 1)
void attn_kernel()
{
    extern __shared__ float smem[];
    float* sc = smem;                      // [QT][SS]          131072 B
    float* Kt = sc + QT*SS;                // [DC][CKP] phase A
    float* Qs = Kt + DC*CKP;               // [QT][DD]
    // phase B/C alias the Kt/Qs region (37120 B >= 29696 B needed):
    int* hist = (int*)(sc + QT*SS);        // [16][256]
    int* sel  = hist + QT*256;             // [QT][KKEEP]
    int* wsi  = sel + QT*KKEEP;            // [16][4]

    const int t    = threadIdx.x;
    const int tile = blockIdx.x;
    const int bh   = tile / (SS/QT);
    const int q0   = (tile % (SS/QT)) * QT;
    const float* Qg = g_Q + (size_t)bh*SS*DD;
    const float* Kg = g_K + (size_t)bh*SS*DD;
    const float* Vg = g_V + (size_t)bh*SS*DD;

    // load Q rows (16 x 64)
    if (t < 256) {
        int r = t >> 4, c = (t & 15) * 4;
        *(float4*)&Qs[r*DD + c] = *(const float4*)&Qg[(size_t)(q0 + r)*DD + c];
    }
    __syncthreads();

    // ---- phase A: scores, 4q x 4k register tile ----
    const float scale = 0.125f;  // 1/sqrt(64)
    const int g  = t >> 7;        // 0..3 -> rows g, g+4, g+8, g+12
    const int k0 = (t & 127) * 4; // 4 keys of CK=512

    for (int kc = 0; kc < SS; kc += CK) {
        float acc[4][4];
#pragma unroll
        for (int i = 0; i < 4; i++)
#pragma unroll
            for (int j = 0; j < 4; j++) acc[i][j] = 0.f;

        for (int dc = 0; dc < DD; dc += DC) {
            // load K chunk transposed: Kt[dlocal][key]
#pragma unroll
            for (int it = 0; it < 4; it++) {
                int idx = it * 512 + t;
                int key = idx >> 2;
                int jj  = idx & 3;
                float4 v = *(const float4*)&Kg[(size_t)(kc + key)*DD + dc + jj*4];
                Kt[(jj*4+0)*CKP + key] = v.x;
                Kt[(jj*4+1)*CKP + key] = v.y;
                Kt[(jj*4+2)*CKP + key] = v.z;
                Kt[(jj*4+3)*CKP + key] = v.w;
            }
            __syncthreads();
#pragma unroll
            for (int d4 = 0; d4 < DC; d4 += 4) {
                float q[4][4], kv[4][4];
#pragma unroll
                for (int i = 0; i < 4; i++)
                    *(float4*)q[i] = *(const float4*)&Qs[(g + 4*i)*DD + dc + d4];
#pragma unroll
                for (int dd = 0; dd < 4; dd++)
                    *(float4*)kv[dd] = *(const float4*)&Kt[(d4+dd)*CKP + k0];
#pragma unroll
                for (int i = 0; i < 4; i++)
#pragma unroll
                    for (int dd = 0; dd < 4; dd++)
#pragma unroll
                        for (int j = 0; j < 4; j++)
                            acc[i][j] += q[i][dd] * kv[dd][j];
            }
            __syncthreads();
        }
#pragma unroll
        for (int i = 0; i < 4; i++)
            *(float4*)&sc[(g + 4*i)*SS + kc + k0] =
                make_float4(acc[i][0]*scale, acc[i][1]*scale,
                            acc[i][2]*scale, acc[i][3]*scale);
    }
    __syncthreads();

    // ---- phase B: per-warp exact top-204 radix select (16 warps = 16 rows) ----
    const int w = t >> 5, lane = t & 31;
    const unsigned ltmask = (1u << lane) - 1u;
    const int qi = w;
    const float* row = sc + qi*SS;
    int* h = hist + w*256;

    // pass 0 fused with row max
    for (int i = lane; i < 256; i += 32) h[i] = 0;
    __syncwarp();
    float rmax = -1e30f;
    for (int i = lane; i < SS; i += 32) {
        float v = row[i];
        rmax = fmaxf(rmax, v);
        atomicAdd(&h[fkey(v) >> 24], 1);
    }
#pragma unroll
    for (int off = 16; off; off >>= 1)
        rmax = fmaxf(rmax, __shfl_xor_sync(~0u, rmax, off));
    const float m = fmaxf(rmax, 0.0f);  // sparse row contains zeros

    int rem = KKEEP;
    unsigned prefix = 0;
#pragma unroll
    for (int pass = 0; pass < 4; pass++) {
        int shift = 24 - pass*8;
        if (pass > 0) {
            for (int i = lane; i < 256; i += 32) h[i] = 0;
            __syncwarp();
            for (int i = lane; i < SS; i += 32) {
                unsigned u = fkey(row[i]);
                if ((u >> (shift + 8)) == prefix)
                    atomicAdd(&h[(u >> shift) & 255], 1);
            }
        }
        __syncwarp();
        if (lane == 0) {
            int cum = 0, bsel = 0, r2 = rem;
            for (int bbin = 255; bbin >= 0; bbin--) {
                int c = h[bbin];
                if (cum + c >= rem) { bsel = bbin; r2 = rem - cum; break; }
                cum += c;
            }
            wsi[w*4+0] = bsel;
            wsi[w*4+1] = r2;
        }
        __syncwarp();
        prefix = (prefix << 8) | (unsigned)wsi[w*4+0];
        rem = wsi[w*4+1];
    }
    const unsigned T = prefix;   // key of the 204th largest
    const int need_eq = rem;     // #equal-to-T taken (lowest index first)

    // selection list (index-ordered tie-break, matches jax top_k) + Z
    int cnt = 0, eqtaken = 0;
    float zacc = 0.f;
    for (int i0 = 0; i0 < SS; i0 += 32) {
        int i = i0 + lane;
        float v = row[i];
        unsigned u = fkey(v);
        bool gt = u > T;
        bool eq = (u == T);
        unsigned em = __ballot_sync(~0u, eq);
        bool seleq = eq && (eqtaken + __popc(em & ltmask)) < need_eq;
        eqtaken += __popc(em);
        bool selected = gt || seleq;
        unsigned smk = __ballot_sync(~0u, selected);
        int pos = cnt + __popc(smk & ltmask);
        cnt += __popc(smk);
        if (selected && pos < KKEEP) {
            sel[qi*KKEEP + pos] = i;
            zacc += __expf(v - m);
        }
    }
#pragma unroll
    for (int off = 16; off; off >>= 1)
        zacc += __shfl_xor_sync(~0u, zacc, off);
    const float e0 = __expf(-m);
    const float Z = zacc + (float)(SS - KKEEP) * e0;
    const float invZ = 1.0f / Z;

    // ---- phase C: out = (sum_sel (e_i - e0) V_i + e0 * Vsum) / Z ----
    const int d0 = 2*lane;
    float2 a = *(const float2*)&g_Vsum[bh*DD + d0];
    a.x *= e0; a.y *= e0;
#pragma unroll 2
    for (int j = 0; j < KKEEP; j++) {
        int idx = sel[qi*KKEEP + j];
        float wgt = __expf(row[idx] - m) - e0;
        float2 vr = *(const float2*)&Vg[(size_t)idx * DD + d0];
        a.x += wgt * vr.x;
        a.y += wgt * vr.y;
    }
    const int b_ = bh / HH, hh = bh % HH;
    float* ao = g_AO + ((size_t)(b_*SS + q0 + qi))*HIDD + hh*DD;
    ao[d0]   = a.x * invZ;
    ao[d0+1] = a.y * invZ;
}

// ---------------- launcher ----------------
extern "C" void kernel_launch(void* const* d_in, const int* in_sizes, int n_in,
                              void* d_out, int out_size)
{
    (void)in_sizes; (void)n_in; (void)out_size;
    const float* x  = (const float*)d_in[0];
    const float* Wq = (const float*)d_in[1];
    const float* bq = (const float*)d_in[2];
    const float* Wk = (const float*)d_in[3];
    const float* bk = (const float*)d_in[4];
    const float* Wv = (const float*)d_in[5];
    const float* bv = (const float*)d_in[6];
    const float* Wo = (const float*)d_in[7];
    const float* bo = (const float*)d_in[8];
    float* out = (float*)d_out;

    const int smem_bytes = (QT*SS + DC*CKP + QT*DD) * 4;  // 168192
    cudaFuncSetAttribute(attn_kernel, cudaFuncAttributeMaxDynamicSharedMemorySize,
                         smem_bytes);

    dim3 gqkv(HIDD/128, (BB*SS)/128, 3);   // 8 x 32 x 3
    gemm_qkv<<<gqkv, 256>>>(x, Wq, bq, Wk, bk, Wv, bv);

    vsum_kernel<<<BB*HH, 512>>>();

    attn_kernel<<<BB*HH*(SS/QT), 512, smem_bytes>>>();

    dim3 go(HIDD/128, (BB*SS)/128);        // 8 x 32
    gemm_o<<<go, 256>>>(Wo, bo, out);
}